// round 1
// baseline (speedup 1.0000x reference)
#include <cuda_runtime.h>
#include <cuda_bf16.h>

// Problem constants (from reference):
//   L = 60000 (= T * lcm), D_MODEL = 256, KERNEL = 5 (pad 2)
//   streams: s=4 (len 15000), s=2 (len 30000), s=1 (len 60000)
// Output: X [3,256,60000] fp32 then S [2,60000] (as fp32), flattened.

#define L_FULL 60000
#define LEN0   15000
#define LEN1   30000
#define VEC_PER_ROW 15000   // 60000 / 4

__global__ __launch_bounds__(256) void embedder_kernel(
    const float* __restrict__ x0, const float* __restrict__ x1,
    const float* __restrict__ x2, const float* __restrict__ W,
    const float* __restrict__ b, float* __restrict__ out, int do_s)
{
    int j = blockIdx.x * 256 + threadIdx.x;   // float4 index within a row
    if (j >= VEC_PER_ROW) return;
    int r = blockIdx.y;                        // 0..767 = (stream*256 + d), 768 = S
    int p = j << 2;                            // base position

    if (r == 768) {
        if (!do_s) return;
        // S = [rows(60000), cols(60000)] as float. Breakpoints 15000/45000 are
        // divisible by 4, so each float4 is within one piece.
        float* s = out + (size_t)768 * L_FULL;
        float4 rv, cv;
        if (p < 15000) {
            rv = make_float4(0.f, 0.f, 0.f, 0.f);
            cv = make_float4((float)(4*p), (float)(4*(p+1)),
                             (float)(4*(p+2)), (float)(4*(p+3)));
        } else if (p < 45000) {
            int q = p - 15000;
            rv = make_float4(1.f, 1.f, 1.f, 1.f);
            cv = make_float4((float)(2*q), (float)(2*(q+1)),
                             (float)(2*(q+2)), (float)(2*(q+3)));
        } else {
            int q = p - 45000;
            rv = make_float4(2.f, 2.f, 2.f, 2.f);
            cv = make_float4((float)q, (float)(q+1), (float)(q+2), (float)(q+3));
        }
        reinterpret_cast<float4*>(s)[j] = rv;
        reinterpret_cast<float4*>(s + L_FULL)[j] = cv;
        return;
    }

    int i = r >> 8;        // stream
    int d = r & 255;       // channel
    float bb = __ldg(b + d);
    const float* w = W + d * 5;

    float4 v = make_float4(0.f, 0.f, 0.f, 0.f);
    float* vv = &v.x;

    if (i == 0) {
        // Only tap k=2 lands on a multiple of 4.
        if (p < LEN0) {
            float w2 = __ldg(w + 2);
            vv[0] = fmaf(w2, __ldg(x0 + p + 0), bb);
            vv[1] = fmaf(w2, __ldg(x0 + p + 1), bb);
            vv[2] = fmaf(w2, __ldg(x0 + p + 2), bb);
            vv[3] = fmaf(w2, __ldg(x0 + p + 3), bb);
        }
    } else if (i == 1) {
        // Even taps: k=0 -> x1[p-1], k=2 -> x1[p], k=4 -> x1[p+1].
        if (p < LEN1) {
            float w0 = __ldg(w + 0), w2 = __ldg(w + 2), w4 = __ldg(w + 4);
            float xv[6];
            #pragma unroll
            for (int t = 0; t < 6; t++) {
                int idx = p - 1 + t;
                xv[t] = (idx >= 0 && idx < LEN1) ? __ldg(x1 + idx) : 0.f;
            }
            #pragma unroll
            for (int q = 0; q < 4; q++)
                vv[q] = fmaf(w0, xv[q], fmaf(w2, xv[q+1], fmaf(w4, xv[q+2], bb)));
        }
    } else {
        // Full 5-tap, boundary-zeroed.
        float w0 = __ldg(w+0), w1 = __ldg(w+1), w2 = __ldg(w+2),
              w3 = __ldg(w+3), w4 = __ldg(w+4);
        float xv[8];
        #pragma unroll
        for (int t = 0; t < 8; t++) {
            int idx = p - 2 + t;
            xv[t] = (idx >= 0 && idx < L_FULL) ? __ldg(x2 + idx) : 0.f;
        }
        #pragma unroll
        for (int q = 0; q < 4; q++)
            vv[q] = fmaf(w0, xv[q],
                    fmaf(w1, xv[q+1],
                    fmaf(w2, xv[q+2],
                    fmaf(w3, xv[q+3],
                    fmaf(w4, xv[q+4], bb)))));
    }

    reinterpret_cast<float4*>(out)[(size_t)r * VEC_PER_ROW + j] = v;
}

extern "C" void kernel_launch(void* const* d_in, const int* in_sizes, int n_in,
                              void* d_out, int out_size) {
    const float* x0 = (const float*)d_in[0];   // x_250  (15000)
    const float* x1 = (const float*)d_in[1];   // x_500  (30000)
    const float* x2 = (const float*)d_in[2];   // x_1000 (60000)
    const float* W  = (const float*)d_in[3];   // (256,1,5)
    const float* b  = (const float*)d_in[4];   // (256,)
    float* out = (float*)d_out;

    // X alone = 46,080,000 elems; with S = 46,200,000. Write S only if present.
    int do_s = (out_size >= 46200000) ? 1 : 0;
    dim3 grid((VEC_PER_ROW + 255) / 256, do_s ? 769 : 768);
    embedder_kernel<<<grid, 256>>>(x0, x1, x2, W, b, out, do_s);
}

// round 3
// speedup vs baseline: 1.2637x; 1.2637x over previous
#include <cuda_runtime.h>
#include <cuda_bf16.h>

// L = 60000, D = 256, kernel = 5 (pad 2)
// streams: s=4 (len 15000), s=2 (len 30000), s=1 (len 60000)
// Output: X [3,256,60000] fp32, then S [2,60000] as fp32.

#define NF4   15000              // float4 per output row (60000/4)
#define L_FULL 60000

// ---------------------------------------------------------------------------
// Main conv kernel: blockIdx.x = position chunk (256 float4), blockIdx.y =
// stream, blockIdx.z = channel group (32 channels). Each thread loads its
// x-window ONCE (<=3 LDG.128) and reuses it across 32 channel stores.
// ---------------------------------------------------------------------------
__global__ __launch_bounds__(256) void conv_kernel(
    const float* __restrict__ x0, const float* __restrict__ x1,
    const float* __restrict__ x2, const float* __restrict__ W,
    const float* __restrict__ b, float* __restrict__ out)
{
    __shared__ __align__(16) float cw[32 * 8];   // [w0..w4, b, pad, pad] per channel

    const int i   = blockIdx.y;          // stream
    const int d0  = blockIdx.z << 5;     // first channel of this group
    const int tid = threadIdx.x;

    if (tid < 32) {
        const float* wr = W + (d0 + tid) * 5;
        #pragma unroll
        for (int k = 0; k < 5; k++) cw[tid * 8 + k] = __ldg(wr + k);
        cw[tid * 8 + 5] = __ldg(b + d0 + tid);
    }
    __syncthreads();

    const int j = blockIdx.x * 256 + tid;    // float4 index in the row
    if (j >= NF4) return;

    const float4 z4 = make_float4(0.f, 0.f, 0.f, 0.f);
    float xv[8];
    bool live;

    if (i == 0) {
        // only tap k=2 contributes; len 15000 -> j < 3750
        live = (j < 3750);
        if (live) {
            float4 m = reinterpret_cast<const float4*>(x0)[j];
            xv[0] = m.x; xv[1] = m.y; xv[2] = m.z; xv[3] = m.w;
        }
    } else if (i == 1) {
        // taps k=0,2,4 -> x1[p-1..p+4+1]; len 30000 -> j < 7500
        live = (j < 7500);
        if (live) {
            float4 mp = (j > 0)        ? reinterpret_cast<const float4*>(x1)[j - 1] : z4;
            float4 mc =                  reinterpret_cast<const float4*>(x1)[j];
            float4 mn = (j + 1 < 7500) ? reinterpret_cast<const float4*>(x1)[j + 1] : z4;
            xv[0] = mp.w;
            xv[1] = mc.x; xv[2] = mc.y; xv[3] = mc.z; xv[4] = mc.w;
            xv[5] = mn.x;
        }
    } else {
        // full 5-tap on x2; len 60000 -> all j live
        live = true;
        float4 mp = (j > 0)         ? reinterpret_cast<const float4*>(x2)[j - 1] : z4;
        float4 mc =                   reinterpret_cast<const float4*>(x2)[j];
        float4 mn = (j + 1 < 15000) ? reinterpret_cast<const float4*>(x2)[j + 1] : z4;
        xv[0] = mp.z; xv[1] = mp.w;
        xv[2] = mc.x; xv[3] = mc.y; xv[4] = mc.z; xv[5] = mc.w;
        xv[6] = mn.x; xv[7] = mn.y;
    }

    float4* po = reinterpret_cast<float4*>(out) + (size_t)(i * 256 + d0) * NF4 + j;

    if (!live) {
        #pragma unroll 8
        for (int c = 0; c < 32; c++) { *po = z4; po += NF4; }
        return;
    }

    if (i == 0) {
        #pragma unroll 8
        for (int c = 0; c < 32; c++) {
            float w2 = cw[c * 8 + 2], bb = cw[c * 8 + 5];
            float4 v = make_float4(fmaf(w2, xv[0], bb), fmaf(w2, xv[1], bb),
                                   fmaf(w2, xv[2], bb), fmaf(w2, xv[3], bb));
            *po = v; po += NF4;
        }
    } else if (i == 1) {
        #pragma unroll 8
        for (int c = 0; c < 32; c++) {
            float4 wv = reinterpret_cast<const float4*>(cw)[c * 2];  // w0..w3
            float  w4 = cw[c * 8 + 4], bb = cw[c * 8 + 5];
            float4 v;
            v.x = fmaf(wv.x, xv[0], fmaf(wv.z, xv[1], fmaf(w4, xv[2], bb)));
            v.y = fmaf(wv.x, xv[1], fmaf(wv.z, xv[2], fmaf(w4, xv[3], bb)));
            v.z = fmaf(wv.x, xv[2], fmaf(wv.z, xv[3], fmaf(w4, xv[4], bb)));
            v.w = fmaf(wv.x, xv[3], fmaf(wv.z, xv[4], fmaf(w4, xv[5], bb)));
            *po = v; po += NF4;
        }
    } else {
        #pragma unroll 8
        for (int c = 0; c < 32; c++) {
            float4 wv = reinterpret_cast<const float4*>(cw)[c * 2];  // w0..w3
            float  w4 = cw[c * 8 + 4], bb = cw[c * 8 + 5];
            float4 v;
            v.x = fmaf(wv.x, xv[0], fmaf(wv.y, xv[1], fmaf(wv.z, xv[2], fmaf(wv.w, xv[3], fmaf(w4, xv[4], bb)))));
            v.y = fmaf(wv.x, xv[1], fmaf(wv.y, xv[2], fmaf(wv.z, xv[3], fmaf(wv.w, xv[4], fmaf(w4, xv[5], bb)))));
            v.z = fmaf(wv.x, xv[2], fmaf(wv.y, xv[3], fmaf(wv.z, xv[4], fmaf(wv.w, xv[5], fmaf(w4, xv[6], bb)))));
            v.w = fmaf(wv.x, xv[3], fmaf(wv.y, xv[4], fmaf(wv.z, xv[5], fmaf(wv.w, xv[6], fmaf(w4, xv[7], bb)))));
            *po = v; po += NF4;
        }
    }
}

// ---------------------------------------------------------------------------
// S kernel: closed-form piecewise ramps. Breakpoints 15000/45000 are
// divisible by 4 so every float4 lies in one piece.
// ---------------------------------------------------------------------------
__global__ __launch_bounds__(256) void s_kernel(float* __restrict__ out)
{
    int j = blockIdx.x * 256 + threadIdx.x;
    if (j >= NF4) return;
    int p = j << 2;

    float* s = out + (size_t)768 * L_FULL;
    float4 rv, cv;
    if (p < 15000) {
        rv = make_float4(0.f, 0.f, 0.f, 0.f);
        cv = make_float4((float)(4 * p), (float)(4 * (p + 1)),
                         (float)(4 * (p + 2)), (float)(4 * (p + 3)));
    } else if (p < 45000) {
        int q = p - 15000;
        rv = make_float4(1.f, 1.f, 1.f, 1.f);
        cv = make_float4((float)(2 * q), (float)(2 * (q + 1)),
                         (float)(2 * (q + 2)), (float)(2 * (q + 3)));
    } else {
        int q = p - 45000;
        rv = make_float4(2.f, 2.f, 2.f, 2.f);
        cv = make_float4((float)q, (float)(q + 1), (float)(q + 2), (float)(q + 3));
    }
    reinterpret_cast<float4*>(s)[j] = rv;
    reinterpret_cast<float4*>(s + L_FULL)[j] = cv;
}

extern "C" void kernel_launch(void* const* d_in, const int* in_sizes, int n_in,
                              void* d_out, int out_size) {
    const float* x0 = (const float*)d_in[0];   // x_250  (15000)
    const float* x1 = (const float*)d_in[1];   // x_500  (30000)
    const float* x2 = (const float*)d_in[2];   // x_1000 (60000)
    const float* W  = (const float*)d_in[3];   // (256,1,5)
    const float* b  = (const float*)d_in[4];   // (256,)
    float* out = (float*)d_out;

    dim3 grid((NF4 + 255) / 256, 3, 8);        // 59 x 3 streams x 8 channel-groups
    conv_kernel<<<grid, 256>>>(x0, x1, x2, W, b, out);

    if (out_size >= 46200000) {
        s_kernel<<<(NF4 + 255) / 256, 256>>>(out);
    }
}

// round 4
// speedup vs baseline: 1.4385x; 1.1383x over previous
#include <cuda_runtime.h>
#include <cuda_bf16.h>

// L = 60000, D = 256, kernel = 5 (pad 2)
// streams: s=4 (len 15000), s=2 (len 30000), s=1 (len 60000)
// Output: X [3,256,60000] fp32, then S [2,60000] as fp32. One fused kernel.

#define NF4    15000             // float4 per output row (60000/4)
#define L_FULL 60000

// blockIdx.x = position chunk (256 float4)
// blockIdx.y = 0..23 -> (stream = y>>3, channel-group = y&7); y == 24 -> S rows
__global__ __launch_bounds__(256) void fused_kernel(
    const float* __restrict__ x0, const float* __restrict__ x1,
    const float* __restrict__ x2, const float* __restrict__ W,
    const float* __restrict__ b, float* __restrict__ out, int do_s)
{
    const int tid = threadIdx.x;
    const int j = blockIdx.x * 256 + tid;    // float4 index in the row
    const int y = blockIdx.y;

    if (y == 24) {
        // ---- S: closed-form piecewise ramps (breakpoints divisible by 4) ----
        if (!do_s || j >= NF4) return;
        int p = j << 2;
        float* s = out + (size_t)768 * L_FULL;
        float4 rv, cv;
        if (p < 15000) {
            rv = make_float4(0.f, 0.f, 0.f, 0.f);
            cv = make_float4((float)(4 * p), (float)(4 * p + 4),
                             (float)(4 * p + 8), (float)(4 * p + 12));
        } else if (p < 45000) {
            int q = p - 15000;
            rv = make_float4(1.f, 1.f, 1.f, 1.f);
            cv = make_float4((float)(2 * q), (float)(2 * q + 2),
                             (float)(2 * q + 4), (float)(2 * q + 6));
        } else {
            int q = p - 45000;
            rv = make_float4(2.f, 2.f, 2.f, 2.f);
            cv = make_float4((float)q, (float)(q + 1), (float)(q + 2), (float)(q + 3));
        }
        reinterpret_cast<float4*>(s)[j] = rv;
        reinterpret_cast<float4*>(s + L_FULL)[j] = cv;
        return;
    }

    __shared__ __align__(16) float cw[32 * 8];   // [w0..w4, b, pad, pad] per channel

    const int i  = y >> 3;            // stream
    const int d0 = (y & 7) << 5;      // first channel of this 32-channel group

    if (tid < 32) {
        const float* wr = W + (d0 + tid) * 5;
        #pragma unroll
        for (int k = 0; k < 5; k++) cw[tid * 8 + k] = __ldg(wr + k);
        cw[tid * 8 + 5] = __ldg(b + d0 + tid);
    }
    __syncthreads();

    if (j >= NF4) return;

    const float4 z4 = make_float4(0.f, 0.f, 0.f, 0.f);
    float xv[8];
    bool live;

    if (i == 0) {
        live = (j < 3750);
        if (live) {
            float4 m = reinterpret_cast<const float4*>(x0)[j];
            xv[0] = m.x; xv[1] = m.y; xv[2] = m.z; xv[3] = m.w;
        }
    } else if (i == 1) {
        live = (j < 7500);
        if (live) {
            float4 mp = (j > 0)        ? reinterpret_cast<const float4*>(x1)[j - 1] : z4;
            float4 mc =                  reinterpret_cast<const float4*>(x1)[j];
            float4 mn = (j + 1 < 7500) ? reinterpret_cast<const float4*>(x1)[j + 1] : z4;
            xv[0] = mp.w;
            xv[1] = mc.x; xv[2] = mc.y; xv[3] = mc.z; xv[4] = mc.w;
            xv[5] = mn.x;
        }
    } else {
        live = true;
        float4 mp = (j > 0)         ? reinterpret_cast<const float4*>(x2)[j - 1] : z4;
        float4 mc =                   reinterpret_cast<const float4*>(x2)[j];
        float4 mn = (j + 1 < 15000) ? reinterpret_cast<const float4*>(x2)[j + 1] : z4;
        xv[0] = mp.z; xv[1] = mp.w;
        xv[2] = mc.x; xv[3] = mc.y; xv[4] = mc.z; xv[5] = mc.w;
        xv[6] = mn.x; xv[7] = mn.y;
    }

    float4* po = reinterpret_cast<float4*>(out) + (size_t)(i * 256 + d0) * NF4 + j;

    if (!live) {
        #pragma unroll 8
        for (int c = 0; c < 32; c++) { __stcs(po, z4); po += NF4; }
        return;
    }

    if (i == 0) {
        #pragma unroll 8
        for (int c = 0; c < 32; c++) {
            float w2 = cw[c * 8 + 2], bb = cw[c * 8 + 5];
            float4 v = make_float4(fmaf(w2, xv[0], bb), fmaf(w2, xv[1], bb),
                                   fmaf(w2, xv[2], bb), fmaf(w2, xv[3], bb));
            __stcs(po, v); po += NF4;
        }
    } else if (i == 1) {
        #pragma unroll 8
        for (int c = 0; c < 32; c++) {
            float4 wv = reinterpret_cast<const float4*>(cw)[c * 2];  // w0..w3
            float  w4 = cw[c * 8 + 4], bb = cw[c * 8 + 5];
            float4 v;
            v.x = fmaf(wv.x, xv[0], fmaf(wv.z, xv[1], fmaf(w4, xv[2], bb)));
            v.y = fmaf(wv.x, xv[1], fmaf(wv.z, xv[2], fmaf(w4, xv[3], bb)));
            v.z = fmaf(wv.x, xv[2], fmaf(wv.z, xv[3], fmaf(w4, xv[4], bb)));
            v.w = fmaf(wv.x, xv[3], fmaf(wv.z, xv[4], fmaf(w4, xv[5], bb)));
            __stcs(po, v); po += NF4;
        }
    } else {
        #pragma unroll 8
        for (int c = 0; c < 32; c++) {
            float4 wv = reinterpret_cast<const float4*>(cw)[c * 2];  // w0..w3
            float  w4 = cw[c * 8 + 4], bb = cw[c * 8 + 5];
            float4 v;
            v.x = fmaf(wv.x, xv[0], fmaf(wv.y, xv[1], fmaf(wv.z, xv[2], fmaf(wv.w, xv[3], fmaf(w4, xv[4], bb)))));
            v.y = fmaf(wv.x, xv[1], fmaf(wv.y, xv[2], fmaf(wv.z, xv[3], fmaf(wv.w, xv[4], fmaf(w4, xv[5], bb)))));
            v.z = fmaf(wv.x, xv[2], fmaf(wv.y, xv[3], fmaf(wv.z, xv[4], fmaf(wv.w, xv[5], fmaf(w4, xv[6], bb)))));
            v.w = fmaf(wv.x, xv[3], fmaf(wv.y, xv[4], fmaf(wv.z, xv[5], fmaf(wv.w, xv[6], fmaf(w4, xv[7], bb)))));
            __stcs(po, v); po += NF4;
        }
    }
}

extern "C" void kernel_launch(void* const* d_in, const int* in_sizes, int n_in,
                              void* d_out, int out_size) {
    const float* x0 = (const float*)d_in[0];   // x_250  (15000)
    const float* x1 = (const float*)d_in[1];   // x_500  (30000)
    const float* x2 = (const float*)d_in[2];   // x_1000 (60000)
    const float* W  = (const float*)d_in[3];   // (256,1,5)
    const float* b  = (const float*)d_in[4];   // (256,)
    float* out = (float*)d_out;

    int do_s = (out_size >= 46200000) ? 1 : 0;
    dim3 grid((NF4 + 255) / 256, 25);          // 59 x (24 conv slices + 1 S slice)
    fused_kernel<<<grid, 256>>>(x0, x1, x2, W, b, out, do_s);
}